// round 1
// baseline (speedup 1.0000x reference)
#include <cuda_runtime.h>
#include <cuda_bf16.h>

// SSIM preservation loss: 1 - mean(ssim_map(clean, adversarial))
// Inputs: clean [32,3,512,512] f32, adversarial [32,3,512,512] f32 -> scalar f32.
// 11x11 Gaussian window (sigma=1.5), zero ("same") padding, depthwise per channel.
// Separable implementation: vertical pass in per-thread register ring buffers,
// horizontal pass through a double-buffered shared-memory row, weights as
// compile-time immediates (FFMA-imm path).

#define IMG_W 512
#define IMG_H 512
#define ROWS_PER_BLOCK 32
#define STRIPS (IMG_H / ROWS_PER_BLOCK)   // 16
#define NPLANES 96                        // 32 batch * 3 channels
#define NBLOCKS (NPLANES * STRIPS)        // 1536
#define NTHREADS 256
#define TOTAL_PIX 25165824.0              // 32*3*512*512

// 1D Gaussian weights, sigma=1.5, normalized (matches reference to ~1e-6 rel).
#define KW0 0.00102838f
#define KW1 0.00759876f
#define KW2 0.03600077f
#define KW3 0.10936070f
#define KW4 0.21300560f
#define KW5 0.26601170f

__device__ double g_partials[NBLOCKS];

__device__ __forceinline__ float kw(int t) {
    // t in [0,10], symmetric
    switch (t) {
        case 0: case 10: return KW0;
        case 1: case 9:  return KW1;
        case 2: case 8:  return KW2;
        case 3: case 7:  return KW3;
        case 4: case 6:  return KW4;
        default:         return KW5;
    }
}

__device__ __forceinline__ float ssim_px(float mu1, float mu2, float ex2, float ey2, float exy) {
    const float C1 = 1.0e-4f;   // 0.01^2
    const float C2 = 9.0e-4f;   // 0.03^2
    float mu1s = mu1 * mu1;
    float mu2s = mu2 * mu2;
    float mu12 = mu1 * mu2;
    float s1  = ex2 - mu1s;
    float s2  = ey2 - mu2s;
    float s12 = exy - mu12;
    float num = (2.0f * mu12 + C1) * (2.0f * s12 + C2);
    float den = (mu1s + mu2s + C1) * (s1 + s2 + C2);
    return __fdividef(num, den);
}

__global__ void __launch_bounds__(NTHREADS)
ssim_main(const float* __restrict__ X, const float* __restrict__ Y) {
    const int b     = blockIdx.x;
    const int plane = b >> 4;        // / STRIPS
    const int strip = b & 15;        // % STRIPS
    const int r0    = strip * ROWS_PER_BLOCK;
    const int t     = threadIdx.x;
    const int c0    = t * 2;         // this thread owns columns c0, c0+1

    const float* __restrict__ px = X + (size_t)plane * (IMG_H * IMG_W);
    const float* __restrict__ py = Y + (size_t)plane * (IMG_H * IMG_W);

    // Horizontal exchange buffers: index = 8 + col, col in [-5, 516]; pads zeroed.
    __shared__ float vbuf[2][5][528];
    __shared__ float warpsum[8];

    if (t < 5) {
        #pragma unroll
        for (int bb = 0; bb < 2; bb++) {
            #pragma unroll
            for (int i = 0; i < 8; i++) {
                vbuf[bb][t][i] = 0.0f;          // cols -8..-1 region (only -5..-1 read)
                vbuf[bb][t][520 + i] = 0.0f;    // cols 512..519 region (only 512..516 read)
            }
        }
    }
    // Visibility of pads is guaranteed by the per-row __syncthreads before first LDS.

    // Register ring windows: 11 rows x 2 cols per channel.
    float2 w_x[11], w_y[11], w_xx[11], w_yy[11], w_xy[11];

    // Prime slots 0..9 with input rows r0-5 .. r0+4 (zero outside image).
    #pragma unroll
    for (int k = 0; k < 10; k++) {
        int ir = r0 - 5 + k;
        float2 vx = make_float2(0.f, 0.f);
        float2 vy = make_float2(0.f, 0.f);
        if ((unsigned)ir < (unsigned)IMG_H) {
            vx = *(const float2*)(px + ir * IMG_W + c0);
            vy = *(const float2*)(py + ir * IMG_W + c0);
        }
        w_x[k]  = vx;
        w_y[k]  = vy;
        w_xx[k] = make_float2(vx.x * vx.x, vx.y * vx.y);
        w_yy[k] = make_float2(vy.x * vy.x, vy.y * vy.y);
        w_xy[k] = make_float2(vx.x * vy.x, vx.y * vy.y);
    }

    // Preload current row r0+5 (pushed at step r=0).
    float2 curx = make_float2(0.f, 0.f), cury = make_float2(0.f, 0.f);
    {
        int ir = r0 + 5;
        if (ir < IMG_H) {
            curx = *(const float2*)(px + ir * IMG_W + c0);
            cury = *(const float2*)(py + ir * IMG_W + c0);
        }
    }

    float acc = 0.0f;

    for (int rr = 0; rr < ROWS_PER_BLOCK; rr += 11) {
        #pragma unroll
        for (int u = 0; u < 11; u++) {
            const int r = rr + u;
            if (r < ROWS_PER_BLOCK) {
                // ---- prefetch next input row (hidden under this step's math) ----
                float2 nx = make_float2(0.f, 0.f), ny = make_float2(0.f, 0.f);
                {
                    int irn = r0 + r + 6;
                    if (irn < IMG_H) {
                        nx = *(const float2*)(px + irn * IMG_W + c0);
                        ny = *(const float2*)(py + irn * IMG_W + c0);
                    }
                }

                // ---- push current row (r0+r+5) into ring slot (u+10)%11 ----
                {
                    const int s = (u + 10) % 11;
                    w_x[s]  = curx;
                    w_y[s]  = cury;
                    w_xx[s] = make_float2(curx.x * curx.x, curx.y * curx.y);
                    w_yy[s] = make_float2(cury.x * cury.x, cury.y * cury.y);
                    w_xy[s] = make_float2(curx.x * cury.x, curx.y * cury.y);
                }

                // ---- vertical 11-tap conv (weights are immediates) ----
                float2 m1, m2, e11, e22, e12;
                {
                    const int s0 = u % 11;
                    float w0 = kw(0);
                    m1  = make_float2(w0 * w_x[s0].x,  w0 * w_x[s0].y);
                    m2  = make_float2(w0 * w_y[s0].x,  w0 * w_y[s0].y);
                    e11 = make_float2(w0 * w_xx[s0].x, w0 * w_xx[s0].y);
                    e22 = make_float2(w0 * w_yy[s0].x, w0 * w_yy[s0].y);
                    e12 = make_float2(w0 * w_xy[s0].x, w0 * w_xy[s0].y);
                }
                #pragma unroll
                for (int tt = 1; tt < 11; tt++) {
                    const int sl = (u + tt) % 11;
                    const float w = kw(tt);
                    m1.x  = fmaf(w, w_x[sl].x,  m1.x);   m1.y  = fmaf(w, w_x[sl].y,  m1.y);
                    m2.x  = fmaf(w, w_y[sl].x,  m2.x);   m2.y  = fmaf(w, w_y[sl].y,  m2.y);
                    e11.x = fmaf(w, w_xx[sl].x, e11.x);  e11.y = fmaf(w, w_xx[sl].y, e11.y);
                    e22.x = fmaf(w, w_yy[sl].x, e22.x);  e22.y = fmaf(w, w_yy[sl].y, e22.y);
                    e12.x = fmaf(w, w_xy[sl].x, e12.x);  e12.y = fmaf(w, w_xy[sl].y, e12.y);
                }

                // ---- exchange via smem (double-buffered, 1 barrier per row) ----
                const int buf = r & 1;
                *(float2*)(&vbuf[buf][0][8 + c0]) = m1;
                *(float2*)(&vbuf[buf][1][8 + c0]) = m2;
                *(float2*)(&vbuf[buf][2][8 + c0]) = e11;
                *(float2*)(&vbuf[buf][3][8 + c0]) = e22;
                *(float2*)(&vbuf[buf][4][8 + c0]) = e12;
                __syncthreads();

                // ---- horizontal 11-tap conv for 2 pixels; own columns from regs ----
                float hr[5][2];
                float2 vq[5] = {m1, m2, e11, e22, e12};
                #pragma unroll
                for (int q = 0; q < 5; q++) {
                    const float* vb = &vbuf[buf][q][0];
                    float2 L0 = *(const float2*)(vb + 2 + c0);   // cols c0-6, c0-5
                    float2 L1 = *(const float2*)(vb + 4 + c0);   // cols c0-4, c0-3
                    float2 L2 = *(const float2*)(vb + 6 + c0);   // cols c0-2, c0-1
                    float2 L3 = *(const float2*)(vb + 10 + c0);  // cols c0+2, c0+3
                    float2 L4 = *(const float2*)(vb + 12 + c0);  // cols c0+4, c0+5
                    float2 L5 = *(const float2*)(vb + 14 + c0);  // cols c0+6, c0+7
                    float o0 = vq[q].x, o1 = vq[q].y;

                    float p0 = kw(0) * L0.y;
                    p0 = fmaf(kw(1),  L1.x, p0);
                    p0 = fmaf(kw(2),  L1.y, p0);
                    p0 = fmaf(kw(3),  L2.x, p0);
                    p0 = fmaf(kw(4),  L2.y, p0);
                    p0 = fmaf(kw(5),  o0,   p0);
                    p0 = fmaf(kw(6),  o1,   p0);
                    p0 = fmaf(kw(7),  L3.x, p0);
                    p0 = fmaf(kw(8),  L3.y, p0);
                    p0 = fmaf(kw(9),  L4.x, p0);
                    p0 = fmaf(kw(10), L4.y, p0);

                    float p1 = kw(0) * L1.x;
                    p1 = fmaf(kw(1),  L1.y, p1);
                    p1 = fmaf(kw(2),  L2.x, p1);
                    p1 = fmaf(kw(3),  L2.y, p1);
                    p1 = fmaf(kw(4),  o0,   p1);
                    p1 = fmaf(kw(5),  o1,   p1);
                    p1 = fmaf(kw(6),  L3.x, p1);
                    p1 = fmaf(kw(7),  L3.y, p1);
                    p1 = fmaf(kw(8),  L4.x, p1);
                    p1 = fmaf(kw(9),  L4.y, p1);
                    p1 = fmaf(kw(10), L5.x, p1);

                    hr[q][0] = p0;
                    hr[q][1] = p1;
                }

                acc += ssim_px(hr[0][0], hr[1][0], hr[2][0], hr[3][0], hr[4][0]);
                acc += ssim_px(hr[0][1], hr[1][1], hr[2][1], hr[3][1], hr[4][1]);

                curx = nx;
                cury = ny;
            }
        }
    }

    // ---- deterministic block reduction ----
    #pragma unroll
    for (int off = 16; off > 0; off >>= 1)
        acc += __shfl_xor_sync(0xffffffffu, acc, off);
    if ((t & 31) == 0) warpsum[t >> 5] = acc;
    __syncthreads();
    if (t == 0) {
        float s = 0.0f;
        #pragma unroll
        for (int i = 0; i < 8; i++) s += warpsum[i];
        g_partials[b] = (double)s;
    }
}

__global__ void ssim_finalize(float* __restrict__ out) {
    __shared__ double sd[256];
    double s = 0.0;
    for (int i = threadIdx.x; i < NBLOCKS; i += 256) s += g_partials[i];
    sd[threadIdx.x] = s;
    __syncthreads();
    #pragma unroll
    for (int off = 128; off > 0; off >>= 1) {
        if (threadIdx.x < off) sd[threadIdx.x] += sd[threadIdx.x + off];
        __syncthreads();
    }
    if (threadIdx.x == 0) out[0] = (float)(1.0 - sd[0] / TOTAL_PIX);
}

extern "C" void kernel_launch(void* const* d_in, const int* in_sizes, int n_in,
                              void* d_out, int out_size) {
    const float* clean = (const float*)d_in[0];
    const float* adv   = (const float*)d_in[1];
    ssim_main<<<NBLOCKS, NTHREADS>>>(clean, adv);
    ssim_finalize<<<1, 256>>>((float*)d_out);
}